// round 2
// baseline (speedup 1.0000x reference)
#include <cuda_runtime.h>

// ---------------------------------------------------------------------------
// RegionAwareAttention, fp32 baseline with packed f32x2 FMA (Blackwell).
//   B=8, Np=4096, Nr=32, C=768, H=12, D=64, SCALE=1/8
// Pipeline:
//   1) g_kv = region @ Wkv + bkv          (256 x 1536, K=768)
//   2) g_q  = patch  @ Wq  + bq           (32768 x 768, K=768)
//   3) attention(g_q, g_kv, p2r) -> g_q   (in-place safe: each (p,h) slice is
//                                          read fully, then written, by ONE thread)
//   4) out  = g_q @ Wp + bp               (32768 x 768, K=768)
// ---------------------------------------------------------------------------

#define BATCH   8
#define NP      4096
#define NR      32
#define EMBED   768
#define NHEADS  12
#define HDIM    64
#define ATT_SCALE 0.125f

typedef unsigned long long u64;

// scratch (device-global: no allocations allowed in kernel_launch)
__device__ float g_q [BATCH * NP * EMBED];       // 96 MB (q, then x in-place)
__device__ float g_kv[BATCH * NR * 2 * EMBED];   // 1.5 MB

// ---- packed fp32x2 helpers (sm_100+) --------------------------------------
__device__ __forceinline__ void ffma2(u64& d, u64 a, u64 b) {
    asm("fma.rn.f32x2 %0, %1, %2, %0;" : "+l"(d) : "l"(a), "l"(b));
}
__device__ __forceinline__ u64 pack2(float lo, float hi) {
    u64 r; asm("mov.b64 %0, {%1, %2};" : "=l"(r) : "f"(lo), "f"(hi)); return r;
}
__device__ __forceinline__ void unpack2(u64 v, float& lo, float& hi) {
    asm("mov.b64 {%0, %1}, %2;" : "=f"(lo), "=f"(hi) : "l"(v));
}

// ---------------------------------------------------------------------------
// Tiled SGEMM with bias: C[M,N] = A[M,K] @ B[K,N] + bias[N]
// BM=BN=128, BK=8, 256 threads, 8x8 per thread, f32x2-packed accumulators.
// Requires M%128==0, N%128==0, K%8==0 (true for all three calls).
// ---------------------------------------------------------------------------
__global__ __launch_bounds__(256, 2)
void sgemm_bias_kernel(int M, int N, int K,
                       const float* __restrict__ A,
                       const float* __restrict__ B,
                       const float* __restrict__ bias,
                       float* __restrict__ C)
{
    constexpr int BM = 128, BN = 128, BK = 8, TM = 8, TN = 8;
    __shared__ __align__(16) float As[BK][BM];
    __shared__ __align__(16) float Bs[BK][BN];

    const int tid  = threadIdx.x;
    const int tcol = tid & 15;     // 0..15  (N direction, 8 cols each)
    const int trow = tid >> 4;     // 0..15  (M direction, 8 rows each)
    const size_t mBase = (size_t)blockIdx.y * BM;
    const int    nBase = blockIdx.x * BN;

    // cooperative load indices
    const int aRow = tid >> 1;           // 0..127
    const int aCol = (tid & 1) * 4;      // 0 or 4
    const int bRow = tid >> 5;           // 0..7
    const int bCol = (tid & 31) * 4;     // 0..124

    const float* Ag = A + (mBase + aRow) * (size_t)K + aCol;
    const float* Bg = B + (size_t)bRow * N + nBase + bCol;

    u64 acc[TM][TN / 2];
    #pragma unroll
    for (int i = 0; i < TM; i++)
        #pragma unroll
        for (int j = 0; j < TN / 2; j++) acc[i][j] = 0ull;

    for (int k0 = 0; k0 < K; k0 += BK) {
        float4 av = *(const float4*)(Ag + k0);
        As[aCol + 0][aRow] = av.x;
        As[aCol + 1][aRow] = av.y;
        As[aCol + 2][aRow] = av.z;
        As[aCol + 3][aRow] = av.w;
        *(float4*)&Bs[bRow][bCol] = *(const float4*)(Bg + (size_t)k0 * N);
        __syncthreads();

        #pragma unroll
        for (int kk = 0; kk < BK; kk++) {
            float4 a0 = *(const float4*)&As[kk][trow * TM];
            float4 a1 = *(const float4*)&As[kk][trow * TM + 4];
            u64 b0 = *(const u64*)&Bs[kk][tcol * TN + 0];
            u64 b1 = *(const u64*)&Bs[kk][tcol * TN + 2];
            u64 b2 = *(const u64*)&Bs[kk][tcol * TN + 4];
            u64 b3 = *(const u64*)&Bs[kk][tcol * TN + 6];
            u64 ad[8] = { pack2(a0.x, a0.x), pack2(a0.y, a0.y),
                          pack2(a0.z, a0.z), pack2(a0.w, a0.w),
                          pack2(a1.x, a1.x), pack2(a1.y, a1.y),
                          pack2(a1.z, a1.z), pack2(a1.w, a1.w) };
            #pragma unroll
            for (int i = 0; i < 8; i++) {
                ffma2(acc[i][0], ad[i], b0);
                ffma2(acc[i][1], ad[i], b1);
                ffma2(acc[i][2], ad[i], b2);
                ffma2(acc[i][3], ad[i], b3);
            }
        }
        __syncthreads();
    }

    // epilogue: bias + store
    #pragma unroll
    for (int i = 0; i < TM; i++) {
        size_t row = mBase + trow * TM + i;
        float*       Crow = C    + row * (size_t)N + nBase + tcol * TN;
        const float* brow = bias + nBase + tcol * TN;
        #pragma unroll
        for (int j = 0; j < 4; j++) {
            float lo, hi; unpack2(acc[i][j], lo, hi);
            float2 o;
            o.x = lo + brow[2 * j];
            o.y = hi + brow[2 * j + 1];
            *(float2*)&Crow[2 * j] = o;
        }
    }
}

// ---------------------------------------------------------------------------
// Fused attention. One CTA handles one (batch, head, 256-patch chunk).
// K staged in smem as [d][r] (f32x2-pair friendly, pad 34 kills write
// conflicts), V as [r][d]. q / p2r / x streamed per-thread (each thread owns
// one patch row -> contiguous, fully-used sectors). x may alias q: each (p,h)
// slice is fully read before being written, all within one thread.
// ---------------------------------------------------------------------------
__global__ __launch_bounds__(256, 2)
void attention_kernel(const float* __restrict__ q,    // [B, Np, 768]
                      const float* __restrict__ kv,   // [B, Nr, 1536]
                      const float* __restrict__ p2r,  // [B, Np, 32]
                      float* __restrict__ x)          // [B, Np, 768] (may == q)
{
    __shared__ __align__(16) float ks[HDIM][34];   // [d][r], pad->34
    __shared__ __align__(16) float vs[NR][HDIM];   // [r][d]

    const int tid = threadIdx.x;
    const int b   = blockIdx.z;
    const int h   = blockIdx.y;
    const int p0  = blockIdx.x * 256;

    // stage K and V head-slices for (b, h)
    const float* kvb = kv + (size_t)b * NR * (2 * EMBED) + h * HDIM;
    for (int idx = tid; idx < NR * HDIM; idx += 256) {
        int r = idx >> 6, d = idx & 63;
        ks[d][r] = kvb[(size_t)r * (2 * EMBED) + d];            // k
        vs[r][d] = kvb[(size_t)r * (2 * EMBED) + EMBED + d];    // v
    }
    __syncthreads();

    const int    p    = p0 + tid;
    const size_t rowP = (size_t)b * NP + p;
    const float* qrow = q + rowP * EMBED + h * HDIM;

    // ---- S = q . K^T  (32 logits, f32x2-paired over r) ----
    u64 s2[16];
    #pragma unroll
    for (int j = 0; j < 16; j++) s2[j] = 0ull;
    #pragma unroll 4
    for (int d = 0; d < HDIM; d++) {
        float qv = qrow[d];
        u64 q2 = pack2(qv, qv);
        #pragma unroll
        for (int j = 0; j < 16; j++)
            ffma2(s2[j], q2, *(const u64*)&ks[d][2 * j]);
    }

    // ---- softmax( S*SCALE*p2r + 1e-8 ) ----
    float t[NR];
    #pragma unroll
    for (int j = 0; j < 16; j++) unpack2(s2[j], t[2 * j], t[2 * j + 1]);

    const float* prow = p2r + rowP * NR;
    float m = -1e30f;
    #pragma unroll
    for (int r = 0; r < NR; r++) {
        t[r] = fmaf(t[r] * ATT_SCALE, prow[r], 1e-8f);
        m = fmaxf(m, t[r]);
    }
    float sum = 0.0f;
    #pragma unroll
    for (int r = 0; r < NR; r++) { t[r] = __expf(t[r] - m); sum += t[r]; }
    float inv = 1.0f / sum;
    #pragma unroll
    for (int r = 0; r < NR; r++) t[r] *= inv;

    // ---- x = attn @ V  (f32x2-paired over d, 16-d chunks) ----
    float* xrow = x + rowP * EMBED + h * HDIM;
    #pragma unroll
    for (int c = 0; c < 4; c++) {
        u64 acc[8];
        #pragma unroll
        for (int j = 0; j < 8; j++) acc[j] = 0ull;
        #pragma unroll
        for (int r = 0; r < NR; r++) {
            u64 a2 = pack2(t[r], t[r]);
            #pragma unroll
            for (int j = 0; j < 8; j++)
                ffma2(acc[j], a2, *(const u64*)&vs[r][c * 16 + 2 * j]);
        }
        float o[16];
        #pragma unroll
        for (int j = 0; j < 8; j++) unpack2(acc[j], o[2 * j], o[2 * j + 1]);
        #pragma unroll
        for (int j4 = 0; j4 < 4; j4++) {
            float4 ov = { o[4 * j4], o[4 * j4 + 1], o[4 * j4 + 2], o[4 * j4 + 3] };
            *(float4*)&xrow[c * 16 + 4 * j4] = ov;
        }
    }
}

// ---------------------------------------------------------------------------
extern "C" void kernel_launch(void* const* d_in, const int* in_sizes, int n_in,
                              void* d_out, int out_size)
{
    const float* patch  = (const float*)d_in[0];
    const float* region = (const float*)d_in[1];
    const float* p2r    = (const float*)d_in[2];
    const float* Wq     = (const float*)d_in[3];
    const float* bq     = (const float*)d_in[4];
    const float* Wkv    = (const float*)d_in[5];
    const float* bkv    = (const float*)d_in[6];
    const float* Wp     = (const float*)d_in[7];
    const float* bp     = (const float*)d_in[8];
    float* out = (float*)d_out;

    float *qb, *kvb;
    cudaGetSymbolAddress((void**)&qb,  g_q);
    cudaGetSymbolAddress((void**)&kvb, g_kv);

    // 1) KV projection: [256, 1536] = region[256,768] @ Wkv[768,1536] + bkv
    {
        dim3 grid(2 * EMBED / 128, (BATCH * NR) / 128);
        sgemm_bias_kernel<<<grid, 256>>>(BATCH * NR, 2 * EMBED, EMBED,
                                         region, Wkv, bkv, kvb);
    }
    // 2) Q projection: [32768, 768] = patch @ Wq + bq
    {
        dim3 grid(EMBED / 128, (BATCH * NP) / 128);
        sgemm_bias_kernel<<<grid, 256>>>(BATCH * NP, EMBED, EMBED,
                                         patch, Wq, bq, qb);
    }
    // 3) fused attention, in-place on g_q
    {
        dim3 grid(NP / 256, NHEADS, BATCH);
        attention_kernel<<<grid, 256>>>(qb, kvb, p2r, qb);
    }
    // 4) output projection: out = g_q(x) @ Wp + bp
    {
        dim3 grid(EMBED / 128, (BATCH * NP) / 128);
        sgemm_bias_kernel<<<grid, 256>>>(BATCH * NP, EMBED, EMBED,
                                         qb, Wp, bp, out);
    }
}

// round 6
// speedup vs baseline: 2.0961x; 2.0961x over previous
#include <cuda_runtime.h>
#include <cuda_bf16.h>

// ---------------------------------------------------------------------------
// RegionAwareAttention — bf16 mma.sync (HMMA) split-precision GEMMs +
// fused f32x2 attention.  B=8, Np=4096, Nr=32, C=768, H=12, D=64.
// A@W computed as Ah@Wh + Ah@Wl + Al@Wh (bf16 hi/lo split, fp32 accum).
// (R5 resubmit: identical algorithm; R4/R5 container failures were infra-level,
//  same mode as R1 which passed unchanged on retry in R2.)
// ---------------------------------------------------------------------------

#define BATCH   8
#define NP      4096
#define NR      32
#define EMBED   768
#define NHEADS  12
#define HDIM    64
#define ATT_SCALE 0.125f

typedef unsigned long long u64;
typedef unsigned int       u32;

// scratch (no allocations allowed)
__device__ float         g_q [BATCH * NP * EMBED];        // 96 MB (q, then x in-place)
__device__ float         g_kv[BATCH * NR * 2 * EMBED];    // 1.5 MB
__device__ __nv_bfloat16 g_wth[2 * EMBED * EMBED];        // W^T hi  [N][K]
__device__ __nv_bfloat16 g_wtl[2 * EMBED * EMBED];        // W^T lo  [N][K]

__device__ __forceinline__ u32 smem_u32(const void* p) {
    u32 a; asm("{ .reg .u64 t; cvta.to.shared.u64 t, %1; cvt.u32.u64 %0, t; }"
               : "=r"(a) : "l"(p));
    return a;
}

#define LDSM4(r0, r1, r2, r3, addr)                                          \
    asm volatile("ldmatrix.sync.aligned.m8n8.x4.shared.b16 {%0,%1,%2,%3}, [%4];" \
                 : "=r"(r0), "=r"(r1), "=r"(r2), "=r"(r3) : "r"(addr))

#define MMA16816(c, a, b)                                                    \
    asm volatile("mma.sync.aligned.m16n8k16.row.col.f32.bf16.bf16.f32 "      \
                 "{%0,%1,%2,%3}, {%4,%5,%6,%7}, {%8,%9}, {%0,%1,%2,%3};"     \
                 : "+f"((c)[0]), "+f"((c)[1]), "+f"((c)[2]), "+f"((c)[3])    \
                 : "r"((a)[0]), "r"((a)[1]), "r"((a)[2]), "r"((a)[3]),       \
                   "r"((b)[0]), "r"((b)[1]))

// ---------------------------------------------------------------------------
// W transpose + bf16 split:  Th/Tl[n][k] = split(W[k][n])
// ---------------------------------------------------------------------------
__global__ void wsplit_kernel(const float* __restrict__ W, int K, int N,
                              __nv_bfloat16* __restrict__ Th,
                              __nv_bfloat16* __restrict__ Tl)
{
    __shared__ float t[32][33];
    const int k0 = blockIdx.y * 32, n0 = blockIdx.x * 32;
    const int tx = threadIdx.x, ty = threadIdx.y;   // (32, 8)
    #pragma unroll
    for (int i = 0; i < 4; i++)
        t[ty + 8 * i][tx] = W[(size_t)(k0 + ty + 8 * i) * N + n0 + tx];
    __syncthreads();
    #pragma unroll
    for (int i = 0; i < 4; i++) {
        int n = ty + 8 * i;
        float v = t[tx][n];
        __nv_bfloat16 h = __float2bfloat16_rn(v);
        size_t o = (size_t)(n0 + n) * K + k0 + tx;
        Th[o] = h;
        Tl[o] = __float2bfloat16_rn(v - __bfloat162float(h));
    }
}

// ---------------------------------------------------------------------------
// bf16 mma.sync GEMM: C[M,N] = A[M,K](fp32) @ Bt[N,K](bf16 hi/lo) + bias[N]
// Tile 128x128, BK=32, 8 warps (2x4), warp tile 64x32, 3 MMA terms.
// Smem rows padded to 40 halves (80 B) -> conflict-free, 16B-aligned ldmatrix.
// ---------------------------------------------------------------------------
#define PAD 40

__global__ __launch_bounds__(256, 2)
void gemm_mma_kernel(int M, int N, int K,
                     const float* __restrict__ A,
                     const __nv_bfloat16* __restrict__ Bh,
                     const __nv_bfloat16* __restrict__ Bl,
                     const float* __restrict__ bias,
                     float* __restrict__ C)
{
    __shared__ __align__(16) __nv_bfloat16 sAh[128 * PAD];
    __shared__ __align__(16) __nv_bfloat16 sAl[128 * PAD];
    __shared__ __align__(16) __nv_bfloat16 sBh[128 * PAD];
    __shared__ __align__(16) __nv_bfloat16 sBl[128 * PAD];

    const int tid  = threadIdx.x;
    const int lane = tid & 31;
    const int wid  = tid >> 5;
    const int wm   = wid >> 2;        // 0..1  -> rows wm*64
    const int wn   = wid & 3;         // 0..3  -> cols wn*32

    const size_t mBase = (size_t)blockIdx.y * 128;
    const int    nBase = blockIdx.x * 128;

    // --- staging indices ---
    const int aRow = tid >> 1, aHalf = tid & 1;          // 16 floats per thread
    const float* Ag = A + (mBase + aRow) * (size_t)K + aHalf * 16;
    const u32 aSB = aRow * (PAD * 2) + aHalf * 32;       // byte offset in smem

    u32 bSB[2]; size_t bG[2];
    #pragma unroll
    for (int j = 0; j < 2; j++) {
        int c = tid + j * 256;        // 0..511 : 128 rows x 4 chunks(16B)
        int row = c >> 2, sub = c & 3;
        bSB[j] = row * (PAD * 2) + sub * 16;
        bG[j]  = (size_t)(nBase + row) * K + sub * 8;
    }

    const u32 sAhB = smem_u32(sAh), sAlB = smem_u32(sAl);
    const u32 sBhB = smem_u32(sBh), sBlB = smem_u32(sBl);

    // ldmatrix lane-address components (bytes); all 16B-aligned (80B row stride)
    const u32 aLane = ((lane & 15) * PAD + (lane >> 4) * 8) * 2;
    const u32 bLane = (((lane & 7) + ((lane & 16) ? 8 : 0)) * PAD
                       + ((lane >> 3) & 1) * 8) * 2;
    const u32 aWarp = wm * 64 * (PAD * 2);
    const u32 bWarp = wn * 32 * (PAD * 2);

    float acc[4][4][4];
    #pragma unroll
    for (int i = 0; i < 4; i++)
        #pragma unroll
        for (int j = 0; j < 4; j++)
            #pragma unroll
            for (int r = 0; r < 4; r++) acc[i][j][r] = 0.0f;

    const int nkb = K / 32;
    for (int kb = 0; kb < nkb; kb++) {
        const int k0 = kb * 32;

        // global loads (registers) while previous compute drains
        float4 av[4];
        #pragma unroll
        for (int i = 0; i < 4; i++) av[i] = *(const float4*)(Ag + k0 + i * 4);
        uint4 bhv[2], blv[2];
        #pragma unroll
        for (int j = 0; j < 2; j++) {
            bhv[j] = *(const uint4*)(Bh + bG[j] + k0);
            blv[j] = *(const uint4*)(Bl + bG[j] + k0);
        }
        __syncthreads();   // previous iter's MMAs done reading smem

        // A: fp32 -> bf16 hi/lo, store
        {
            float f[16] = { av[0].x, av[0].y, av[0].z, av[0].w,
                            av[1].x, av[1].y, av[1].z, av[1].w,
                            av[2].x, av[2].y, av[2].z, av[2].w,
                            av[3].x, av[3].y, av[3].z, av[3].w };
            u32 hw[8], lw[8];
            #pragma unroll
            for (int p = 0; p < 8; p++) {
                __nv_bfloat16 h0 = __float2bfloat16_rn(f[2 * p]);
                __nv_bfloat16 h1 = __float2bfloat16_rn(f[2 * p + 1]);
                float r0 = f[2 * p]     - __bfloat162float(h0);
                float r1 = f[2 * p + 1] - __bfloat162float(h1);
                __nv_bfloat162 hv(h0, h1);
                __nv_bfloat162 lv(__float2bfloat16_rn(r0), __float2bfloat16_rn(r1));
                hw[p] = *reinterpret_cast<u32*>(&hv);
                lw[p] = *reinterpret_cast<u32*>(&lv);
            }
            *reinterpret_cast<uint4*>((char*)sAh + aSB)      = make_uint4(hw[0], hw[1], hw[2], hw[3]);
            *reinterpret_cast<uint4*>((char*)sAh + aSB + 16) = make_uint4(hw[4], hw[5], hw[6], hw[7]);
            *reinterpret_cast<uint4*>((char*)sAl + aSB)      = make_uint4(lw[0], lw[1], lw[2], lw[3]);
            *reinterpret_cast<uint4*>((char*)sAl + aSB + 16) = make_uint4(lw[4], lw[5], lw[6], lw[7]);
        }
        #pragma unroll
        for (int j = 0; j < 2; j++) {
            *reinterpret_cast<uint4*>((char*)sBh + bSB[j]) = bhv[j];
            *reinterpret_cast<uint4*>((char*)sBl + bSB[j]) = blv[j];
        }
        __syncthreads();

        // three terms: Ah*Bh, Ah*Bl, Al*Bh
        #pragma unroll
        for (int term = 0; term < 3; term++) {
            const u32 aB = (term == 2 ? sAlB : sAhB) + aWarp + aLane;
            const u32 bB = (term == 1 ? sBlB : sBhB) + bWarp + bLane;
            #pragma unroll
            for (int ks = 0; ks < 32; ks += 16) {
                u32 a[4][4], b[4][2];
                #pragma unroll
                for (int i = 0; i < 4; i++)
                    LDSM4(a[i][0], a[i][1], a[i][2], a[i][3],
                          aB + i * 16 * (PAD * 2) + ks * 2);
                #pragma unroll
                for (int jp = 0; jp < 2; jp++) {
                    u32 r0, r1, r2, r3;
                    LDSM4(r0, r1, r2, r3, bB + jp * 16 * (PAD * 2) + ks * 2);
                    b[2 * jp][0] = r0; b[2 * jp][1] = r1;
                    b[2 * jp + 1][0] = r2; b[2 * jp + 1][1] = r3;
                }
                #pragma unroll
                for (int i = 0; i < 4; i++)
                    #pragma unroll
                    for (int j = 0; j < 4; j++)
                        MMA16816(acc[i][j], a[i], b[j]);
            }
        }
    }

    // epilogue: bias + store (per-lane fragment layout of m16n8)
    const int g = lane >> 2, t = lane & 3;
    #pragma unroll
    for (int i = 0; i < 4; i++) {
        #pragma unroll
        for (int j = 0; j < 4; j++) {
            size_t r0 = mBase + wm * 64 + i * 16 + g;
            int col   = nBase + wn * 32 + j * 8 + t * 2;
            float2 bv = *(const float2*)(bias + col);
            float2 o0 = { acc[i][j][0] + bv.x, acc[i][j][1] + bv.y };
            float2 o1 = { acc[i][j][2] + bv.x, acc[i][j][3] + bv.y };
            *(float2*)(C + r0 * N + col)       = o0;
            *(float2*)(C + (r0 + 8) * N + col) = o1;
        }
    }
}

// ---------------------------------------------------------------------------
// Fused attention (unchanged from passing R2 kernel). x may alias q.
// ---------------------------------------------------------------------------
__device__ __forceinline__ void ffma2(u64& d, u64 a, u64 b) {
    asm("fma.rn.f32x2 %0, %1, %2, %0;" : "+l"(d) : "l"(a), "l"(b));
}
__device__ __forceinline__ u64 pack2(float lo, float hi) {
    u64 r; asm("mov.b64 %0, {%1, %2};" : "=l"(r) : "f"(lo), "f"(hi)); return r;
}
__device__ __forceinline__ void unpack2(u64 v, float& lo, float& hi) {
    asm("mov.b64 {%0, %1}, %2;" : "=f"(lo), "=f"(hi) : "l"(v));
}

__global__ __launch_bounds__(256, 2)
void attention_kernel(const float* __restrict__ q,
                      const float* __restrict__ kv,
                      const float* __restrict__ p2r,
                      float* __restrict__ x)
{
    __shared__ __align__(16) float ks[HDIM][34];
    __shared__ __align__(16) float vs[NR][HDIM];

    const int tid = threadIdx.x;
    const int b   = blockIdx.z;
    const int h   = blockIdx.y;
    const int p0  = blockIdx.x * 256;

    const float* kvb = kv + (size_t)b * NR * (2 * EMBED) + h * HDIM;
    for (int idx = tid; idx < NR * HDIM; idx += 256) {
        int r = idx >> 6, d = idx & 63;
        ks[d][r] = kvb[(size_t)r * (2 * EMBED) + d];
        vs[r][d] = kvb[(size_t)r * (2 * EMBED) + EMBED + d];
    }
    __syncthreads();

    const int    p    = p0 + tid;
    const size_t rowP = (size_t)b * NP + p;
    const float* qrow = q + rowP * EMBED + h * HDIM;

    u64 s2[16];
    #pragma unroll
    for (int j = 0; j < 16; j++) s2[j] = 0ull;
    #pragma unroll 4
    for (int d = 0; d < HDIM; d++) {
        float qv = qrow[d];
        u64 q2 = pack2(qv, qv);
        #pragma unroll
        for (int j = 0; j < 16; j++)
            ffma2(s2[j], q2, *(const u64*)&ks[d][2 * j]);
    }

    float t[NR];
    #pragma unroll
    for (int j = 0; j < 16; j++) unpack2(s2[j], t[2 * j], t[2 * j + 1]);

    const float* prow = p2r + rowP * NR;
    float m = -1e30f;
    #pragma unroll
    for (int r = 0; r < NR; r++) {
        t[r] = fmaf(t[r] * ATT_SCALE, prow[r], 1e-8f);
        m = fmaxf(m, t[r]);
    }
    float sum = 0.0f;
    #pragma unroll
    for (int r = 0; r < NR; r++) { t[r] = __expf(t[r] - m); sum += t[r]; }
    float inv = 1.0f / sum;
    #pragma unroll
    for (int r = 0; r < NR; r++) t[r] *= inv;

    float* xrow = x + rowP * EMBED + h * HDIM;
    #pragma unroll
    for (int c = 0; c < 4; c++) {
        u64 acc[8];
        #pragma unroll
        for (int j = 0; j < 8; j++) acc[j] = 0ull;
        #pragma unroll
        for (int r = 0; r < NR; r++) {
            u64 a2 = pack2(t[r], t[r]);
            #pragma unroll
            for (int j = 0; j < 8; j++)
                ffma2(acc[j], a2, *(const u64*)&vs[r][c * 16 + 2 * j]);
        }
        float o[16];
        #pragma unroll
        for (int j = 0; j < 8; j++) unpack2(acc[j], o[2 * j], o[2 * j + 1]);
        #pragma unroll
        for (int j4 = 0; j4 < 4; j4++) {
            float4 ov = { o[4 * j4], o[4 * j4 + 1], o[4 * j4 + 2], o[4 * j4 + 3] };
            *(float4*)&xrow[c * 16 + 4 * j4] = ov;
        }
    }
}

// ---------------------------------------------------------------------------
extern "C" void kernel_launch(void* const* d_in, const int* in_sizes, int n_in,
                              void* d_out, int out_size)
{
    const float* patch  = (const float*)d_in[0];
    const float* region = (const float*)d_in[1];
    const float* p2r    = (const float*)d_in[2];
    const float* Wq     = (const float*)d_in[3];
    const float* bq     = (const float*)d_in[4];
    const float* Wkv    = (const float*)d_in[5];
    const float* bkv    = (const float*)d_in[6];
    const float* Wp     = (const float*)d_in[7];
    const float* bp     = (const float*)d_in[8];
    float* out = (float*)d_out;

    float *qb, *kvb;
    __nv_bfloat16 *wth, *wtl;
    cudaGetSymbolAddress((void**)&qb,  g_q);
    cudaGetSymbolAddress((void**)&kvb, g_kv);
    cudaGetSymbolAddress((void**)&wth, g_wth);
    cudaGetSymbolAddress((void**)&wtl, g_wtl);

    // 1) KV projection: [256, 1536] = region @ Wkv + bkv
    wsplit_kernel<<<dim3((2 * EMBED) / 32, EMBED / 32), dim3(32, 8)>>>(
        Wkv, EMBED, 2 * EMBED, wth, wtl);
    gemm_mma_kernel<<<dim3((2 * EMBED) / 128, (BATCH * NR) / 128), 256>>>(
        BATCH * NR, 2 * EMBED, EMBED, region, wth, wtl, bkv, kvb);

    // 2) Q projection: [32768, 768] = patch @ Wq + bq
    wsplit_kernel<<<dim3(EMBED / 32, EMBED / 32), dim3(32, 8)>>>(
        Wq, EMBED, EMBED, wth, wtl);
    gemm_mma_kernel<<<dim3(EMBED / 128, (BATCH * NP) / 128), 256>>>(
        BATCH * NP, EMBED, EMBED, patch, wth, wtl, bq, qb);

    // 3) fused attention, in-place on g_q
    attention_kernel<<<dim3(NP / 256, NHEADS, BATCH), 256>>>(qb, kvb, p2r, qb);

    // 4) output projection: out = g_q(x) @ Wp + bp
    wsplit_kernel<<<dim3(EMBED / 32, EMBED / 32), dim3(32, 8)>>>(
        Wp, EMBED, EMBED, wth, wtl);
    gemm_mma_kernel<<<dim3(EMBED / 128, (BATCH * NP) / 128), 256>>>(
        BATCH * NP, EMBED, EMBED, qb, wth, wtl, bp, out);
}